// round 1
// baseline (speedup 1.0000x reference)
#include <cuda_runtime.h>
#include <math.h>

#define D 128
#define S 64
#define G 256
#define NMAX 400000

#define LDA 132      // padded stride for 128-wide fp32 tiles (bank-conflict-free A frags)
#define LDSUB 68     // padded stride for 64-wide sub tile
#define LDW 132      // padded stride for weight chunk (tf32 bits)

// ---------------- persistent device scratch (allocation-free) ----------------
__device__ float g_hfused[(size_t)NMAX * D];
__device__ float g_Z1[(size_t)NMAX * D];
__device__ float g_hs[G * D];
__device__ float g_hss[G * D];
__device__ float g_cnt[G];
__device__ float g_bn1sum[D], g_bn1sq[D];
__device__ float g_bn2sum[D], g_bn2sq[D];
__device__ float g_a1[D], g_c1[D], g_a2[D], g_c2[D];
__device__ float g_gm[G * D], g_gisd[G * D];
__device__ float g_num[G * D];
__device__ float g_den[G];

extern __shared__ float dynsmem[];

// ---------------- tf32 helpers ----------------
__device__ __forceinline__ unsigned f2tf(float x) {
    unsigned u;
    asm volatile("cvt.rna.tf32.f32 %0, %1;" : "=r"(u) : "f"(x));
    return u;
}

__device__ __forceinline__ void mma_tf32(float* d, unsigned a0, unsigned a1,
                                         unsigned a2, unsigned a3,
                                         unsigned b0, unsigned b1) {
    asm volatile(
        "mma.sync.aligned.m16n8k8.row.col.f32.tf32.tf32.f32 "
        "{%0,%1,%2,%3}, {%4,%5,%6,%7}, {%8,%9}, {%0,%1,%2,%3};\n"
        : "+f"(d[0]), "+f"(d[1]), "+f"(d[2]), "+f"(d[3])
        : "r"(a0), "r"(a1), "r"(a2), "r"(a3), "r"(b0), "r"(b1));
}

// One 64-deep K chunk for a warp computing a 32x64 sub-tile of a 128x128 block tile.
// A: fp32 smem [128][lda], k columns [kcol0, kcol0+64). B: tf32-bits smem [64][ldw].
__device__ __forceinline__ void warp_mma_chunk(float (&acc)[2][8][4],
                                               const float* sA, int lda, int kcol0,
                                               const unsigned* sB, int ldw,
                                               int wm, int wn, int lane) {
    int g4 = lane >> 2, t4 = lane & 3;
#pragma unroll
    for (int ks = 0; ks < 8; ks++) {
        int kk = ks * 8;
        unsigned a[2][4];
#pragma unroll
        for (int mt = 0; mt < 2; mt++) {
            int rb = wm * 32 + mt * 16;
            const float* p = sA + (rb + g4) * lda + kcol0 + kk + t4;
            a[mt][0] = f2tf(p[0]);
            a[mt][1] = f2tf(p[8 * lda]);
            a[mt][2] = f2tf(p[4]);
            a[mt][3] = f2tf(p[8 * lda + 4]);
        }
#pragma unroll
        for (int nt = 0; nt < 8; nt++) {
            int nb = wn * 64 + nt * 8;
            unsigned b0 = sB[(kk + t4) * ldw + nb + g4];
            unsigned b1 = sB[(kk + 4 + t4) * ldw + nb + g4];
            mma_tf32(acc[0][nt], a[0][0], a[0][1], a[0][2], a[0][3], b0, b1);
            mma_tf32(acc[1][nt], a[1][0], a[1][1], a[1][2], a[1][3], b0, b1);
        }
    }
}

// ---------------- K0: zero accumulators ----------------
__global__ void k_zero() {
    int i = blockIdx.x * blockDim.x + threadIdx.x;
    if (i < G * D) { g_hs[i] = 0.f; g_hss[i] = 0.f; g_num[i] = 0.f; }
    if (i < G) { g_cnt[i] = 0.f; g_den[i] = 0.f; }
    if (i < D) { g_bn1sum[i] = 0.f; g_bn1sq[i] = 0.f; g_bn2sum[i] = 0.f; g_bn2sq[i] = 0.f; }
}

// ---------------- K1: per-graph stats of h (sorted batch -> run-length flush) ----------------
__global__ __launch_bounds__(128) void k_segstats(const float* __restrict__ h,
                                                  const int* __restrict__ batch, int N) {
    __shared__ int sb[512];
    int r0 = blockIdx.x * 512;
    int rend = min(r0 + 512, N);
    int nr = rend - r0;
    for (int i = threadIdx.x; i < nr; i += blockDim.x) sb[i] = batch[r0 + i];
    __syncthreads();
    int c = threadIdx.x;
    float s = 0.f, ss = 0.f, cf = 0.f;
    int cur = sb[0];
    for (int i = 0; i < nr; i++) {
        int g = sb[i];
        if (g != cur) {
            atomicAdd(&g_hs[cur * D + c], s);
            atomicAdd(&g_hss[cur * D + c], ss);
            if (c == 0) atomicAdd(&g_cnt[cur], cf);
            s = 0.f; ss = 0.f; cf = 0.f; cur = g;
        }
        float v = h[(r0 + i) * D + c];
        s += v; ss += v * v; cf += 1.f;
    }
    atomicAdd(&g_hs[cur * D + c], s);
    atomicAdd(&g_hss[cur * D + c], ss);
    if (c == 0) atomicAdd(&g_cnt[cur], cf);
}

// ---------------- K2: BN1 batch stats of X1 = sub@W1 + b1 (mma, discard X1) ----------------
__global__ __launch_bounds__(256, 1) void k_bn1stats(const float* __restrict__ sub,
                                                     const float* __restrict__ W1,
                                                     const float* __restrict__ b1, int N) {
    float* Ss = dynsmem;                                 // [128][LDSUB]
    unsigned* Wb = (unsigned*)(Ss + 128 * LDSUB);        // [64][LDW]
    float* Xs = (float*)(Wb + 64 * LDW);                 // [128][LDA]
    int tid = threadIdx.x;
    int r0 = blockIdx.x * 128;

    for (int i = tid; i < 128 * S; i += 256) {
        int r = i / S, c = i % S;
        int rr = min(r0 + r, N - 1);
        Ss[r * LDSUB + c] = sub[rr * S + c];
    }
    for (int i = tid; i < S * D; i += 256)
        Wb[(i / D) * LDW + (i % D)] = f2tf(W1[i]);
    __syncthreads();

    float acc[2][8][4];
#pragma unroll
    for (int mt = 0; mt < 2; mt++)
#pragma unroll
        for (int nt = 0; nt < 8; nt++)
#pragma unroll
            for (int e = 0; e < 4; e++) acc[mt][nt][e] = 0.f;

    int lane = tid & 31, warp = tid >> 5, wm = warp >> 1, wn = warp & 1;
    warp_mma_chunk(acc, Ss, LDSUB, 0, Wb, LDW, wm, wn, lane);

    int g4 = lane >> 2, t4 = lane & 3;
#pragma unroll
    for (int mt = 0; mt < 2; mt++)
#pragma unroll
        for (int nt = 0; nt < 8; nt++)
#pragma unroll
            for (int e = 0; e < 4; e++) {
                int r = wm * 32 + mt * 16 + g4 + ((e >> 1) << 3);
                int c = wn * 64 + nt * 8 + t4 * 2 + (e & 1);
                Xs[r * LDA + c] = acc[mt][nt][e];
            }
    __syncthreads();

    int c = tid & 127, half = tid >> 7;
    float bb = b1[c];
    float s = 0.f, ss = 0.f;
    for (int r = half * 64; r < half * 64 + 64; r++) {
        if (r0 + r < N) {
            float v = Xs[r * LDA + c] + bb;
            s += v; ss += v * v;
        }
    }
    atomicAdd(&g_bn1sum[c], s);
    atomicAdd(&g_bn1sq[c], ss);
}

// ---------------- finalize kernels ----------------
__global__ void k_gfin() {
    int i = blockIdx.x * blockDim.x + threadIdx.x;
    if (i >= G * D) return;
    int g = i / D;
    float cnt = fmaxf(g_cnt[g], 1.f);
    float m = g_hs[i] / cnt;
    float v = g_hss[i] / cnt - m * m;
    float sd = sqrtf(fmaxf(v, 1e-8f));
    g_gm[i] = m;
    g_gisd[i] = 1.f / (sd + 1e-8f);
}

__global__ void k_bnfin1(const float* __restrict__ gam, const float* __restrict__ bet, float invN) {
    int i = threadIdx.x;
    float mu = g_bn1sum[i] * invN;
    float var = g_bn1sq[i] * invN - mu * mu;
    float inv = rsqrtf(var + 1e-5f);
    g_a1[i] = gam[i] * inv;
    g_c1[i] = bet[i] - mu * gam[i] * inv;
}

__global__ void k_bnfin2(const float* __restrict__ gam, const float* __restrict__ bet, float invN) {
    int i = threadIdx.x;
    float mu = g_bn2sum[i] * invN;
    float var = g_bn2sq[i] * invN - mu * mu;
    float inv = rsqrtf(var + 1e-5f);
    g_a2[i] = gam[i] * inv;
    g_c2[i] = bet[i] - mu * gam[i] * inv;
}

// ---------------- K3: big fused pass ----------------
// recompute X1 -> sub_e -> gate (mma) -> h_fused -> h_dev -> Z1 (mma)
__global__ __launch_bounds__(256, 1) void k_fused(
    const float* __restrict__ h, const float* __restrict__ sub, const int* __restrict__ batch,
    const float* __restrict__ W1, const float* __restrict__ b1,
    const float* __restrict__ Wg, const float* __restrict__ bg,
    const float* __restrict__ Ws1, const float* __restrict__ bs1, int N) {
    float* Hs = dynsmem;                         // [128][LDA]  h -> h_dev
    float* Es = Hs + 128 * LDA;                  // [128][LDA]  sub_e -> h_fused -> Z1
    float* Ss = Es + 128 * LDA;                  // [128][LDSUB]
    unsigned* Wb = (unsigned*)(Ss + 128 * LDSUB);// [64][LDW]
    float* pa1 = (float*)(Wb + 64 * LDW);
    float* pc1 = pa1 + D;
    float* pb1 = pc1 + D;
    float* pbg = pb1 + D;
    float* pbs1 = pbg + D;
    int* gid = (int*)(pbs1 + D);                 // [128]

    int tid = threadIdx.x, lane = tid & 31, warp = tid >> 5;
    int wm = warp >> 1, wn = warp & 1;
    int g4 = lane >> 2, t4 = lane & 3;
    int r0 = blockIdx.x * 128;

    for (int i = tid; i < 128 * D; i += 256) {
        int r = i / D, c = i % D;
        int rr = min(r0 + r, N - 1);
        Hs[r * LDA + c] = h[rr * D + c];
    }
    for (int i = tid; i < 128 * S; i += 256) {
        int r = i / S, c = i % S;
        int rr = min(r0 + r, N - 1);
        Ss[r * LDSUB + c] = sub[rr * S + c];
    }
    for (int i = tid; i < S * D; i += 256)
        Wb[(i / D) * LDW + (i % D)] = f2tf(W1[i]);
    if (tid < 128) {
        pa1[tid] = g_a1[tid]; pc1[tid] = g_c1[tid]; pb1[tid] = b1[tid];
        pbg[tid] = bg[tid]; pbs1[tid] = bs1[tid];
        gid[tid] = batch[min(r0 + tid, N - 1)];
    }
    __syncthreads();

    float acc[2][8][4];
#pragma unroll
    for (int mt = 0; mt < 2; mt++)
#pragma unroll
        for (int nt = 0; nt < 8; nt++)
#pragma unroll
            for (int e = 0; e < 4; e++) acc[mt][nt][e] = 0.f;

    // ---- mma1: X1 = sub @ W1 ----
    warp_mma_chunk(acc, Ss, LDSUB, 0, Wb, LDW, wm, wn, lane);
    __syncthreads();

    // sub_e = relu(a1*(X1+b1)+c1) into Es
#pragma unroll
    for (int mt = 0; mt < 2; mt++)
#pragma unroll
        for (int nt = 0; nt < 8; nt++)
#pragma unroll
            for (int e = 0; e < 4; e++) {
                int r = wm * 32 + mt * 16 + g4 + ((e >> 1) << 3);
                int c = wn * 64 + nt * 8 + t4 * 2 + (e & 1);
                float x = acc[mt][nt][e] + pb1[c];
                Es[r * LDA + c] = fmaxf(pa1[c] * x + pc1[c], 0.f);
                acc[mt][nt][e] = 0.f;
            }
    __syncthreads();

    // ---- mma2: gate_in = [h, sub_e] @ Wg ----
#pragma unroll 1
    for (int ck = 0; ck < 4; ck++) {
        for (int i = tid; i < 64 * D; i += 256)
            Wb[(i / D) * LDW + (i % D)] = f2tf(Wg[ck * 64 * D + i]);
        __syncthreads();
        const float* A = (ck < 2) ? Hs : Es;
        warp_mma_chunk(acc, A, LDA, (ck & 1) * 64, Wb, LDW, wm, wn, lane);
        __syncthreads();
    }

    // gate -> h_fused (overwrite Es)
#pragma unroll
    for (int mt = 0; mt < 2; mt++)
#pragma unroll
        for (int nt = 0; nt < 8; nt++)
#pragma unroll
            for (int e = 0; e < 4; e++) {
                int r = wm * 32 + mt * 16 + g4 + ((e >> 1) << 3);
                int c = wn * 64 + nt * 8 + t4 * 2 + (e & 1);
                float gx = acc[mt][nt][e] + pbg[c];
                float gate = 1.f / (1.f + expf(-gx));
                Es[r * LDA + c] = Hs[r * LDA + c] + gate * Es[r * LDA + c];
                acc[mt][nt][e] = 0.f;
            }
    __syncthreads();

    // write h_fused, transform Hs -> h_dev
    for (int i = tid; i < 128 * D; i += 256) {
        int r = i / D, c = i % D;
        if (r0 + r < N) g_hfused[(r0 + r) * D + c] = Es[r * LDA + c];
        int g = gid[r];
        Hs[r * LDA + c] = (Hs[r * LDA + c] - g_gm[g * D + c]) * g_gisd[g * D + c];
    }
    __syncthreads();

    // ---- mma3: Z1 = [h_fused, h_dev] @ Ws1 ----
#pragma unroll 1
    for (int ck = 0; ck < 4; ck++) {
        for (int i = tid; i < 64 * D; i += 256)
            Wb[(i / D) * LDW + (i % D)] = f2tf(Ws1[ck * 64 * D + i]);
        __syncthreads();
        const float* A = (ck < 2) ? Es : Hs;
        warp_mma_chunk(acc, A, LDA, (ck & 1) * 64, Wb, LDW, wm, wn, lane);
        __syncthreads();
    }

    // Z1 into Es
#pragma unroll
    for (int mt = 0; mt < 2; mt++)
#pragma unroll
        for (int nt = 0; nt < 8; nt++)
#pragma unroll
            for (int e = 0; e < 4; e++) {
                int r = wm * 32 + mt * 16 + g4 + ((e >> 1) << 3);
                int c = wn * 64 + nt * 8 + t4 * 2 + (e & 1);
                Es[r * LDA + c] = acc[mt][nt][e] + pbs1[c];
            }
    __syncthreads();

    // write Z1 + BN2 stats
    for (int i = tid; i < 128 * D; i += 256) {
        int r = i / D, c = i % D;
        if (r0 + r < N) g_Z1[(r0 + r) * D + c] = Es[r * LDA + c];
    }
    {
        int c = tid & 127, half = tid >> 7;
        float s = 0.f, ss = 0.f;
        for (int r = half * 64; r < half * 64 + 64; r++) {
            if (r0 + r < N) {
                float v = Es[r * LDA + c];
                s += v; ss += v * v;
            }
        }
        atomicAdd(&g_bn2sum[c], s);
        atomicAdd(&g_bn2sq[c], ss);
    }
}

// ---------------- K5: logits, exp (shift-invariant softmax), weighted segment sums ----------------
__global__ __launch_bounds__(128) void k_score(const int* __restrict__ batch,
                                               const float* __restrict__ Ws2,
                                               const float* __restrict__ bs2, int N) {
    __shared__ float es[128];
    __shared__ int gid[128];
    int tid = threadIdx.x, lane = tid & 31, warp = tid >> 5;
    int r0 = blockIdx.x * 128;
    int nr = min(128, N - r0);
    if (tid < nr) gid[tid] = batch[r0 + tid];

    float a2v[4], c2v[4], wv[4];
#pragma unroll
    for (int j = 0; j < 4; j++) {
        int c = lane + 32 * j;
        a2v[j] = g_a2[c]; c2v[j] = g_c2[c]; wv[j] = Ws2[c];
    }
    float bsv = bs2[0];

    // phase 1: warp-per-row logits
    for (int rr = warp * 32; rr < warp * 32 + 32; rr++) {
        if (rr >= nr) break;
        int r = r0 + rr;
        float p = 0.f;
#pragma unroll
        for (int j = 0; j < 4; j++) {
            float z = fmaxf(a2v[j] * g_Z1[r * D + lane + 32 * j] + c2v[j], 0.f);
            p += z * wv[j];
        }
#pragma unroll
        for (int o = 16; o > 0; o >>= 1) p += __shfl_xor_sync(0xffffffffu, p, o);
        if (lane == 0) es[rr] = expf(p + bsv);
    }
    __syncthreads();

    // phase 2: column-owner weighted segment sums
    int c = tid;
    float accn = 0.f, accd = 0.f;
    int cur = gid[0];
    for (int rr = 0; rr < nr; rr++) {
        int g = gid[rr];
        if (g != cur) {
            atomicAdd(&g_num[cur * D + c], accn);
            if (c == 0) atomicAdd(&g_den[cur], accd);
            accn = 0.f; accd = 0.f; cur = g;
        }
        float e = es[rr];
        accn += e * g_hfused[(r0 + rr) * D + c];
        accd += e;
    }
    atomicAdd(&g_num[cur * D + c], accn);
    if (c == 0) atomicAdd(&g_den[cur], accd);
}

// ---------------- K6: final combine ----------------
__global__ void k_out(float* __restrict__ out, const float* __restrict__ mix) {
    int i = blockIdx.x * blockDim.x + threadIdx.x;
    if (i >= G * D) return;
    int g = i / D;
    float alpha = 1.f / (1.f + expf(-mix[0]));
    float den = g_den[g];
    float wf = (den > 0.f) ? (g_num[i] / den) : 0.f;
    out[i] = alpha * wf + (1.f - alpha) * g_gm[i];
}

// ---------------- launch ----------------
extern "C" void kernel_launch(void* const* d_in, const int* in_sizes, int n_in,
                              void* d_out, int out_size) {
    const float* h   = (const float*)d_in[0];
    const float* sub = (const float*)d_in[1];
    const int* batch = (const int*)d_in[2];
    const float* W1  = (const float*)d_in[3];
    const float* b1  = (const float*)d_in[4];
    const float* g1  = (const float*)d_in[5];
    const float* be1 = (const float*)d_in[6];
    const float* Wg  = (const float*)d_in[7];
    const float* bg  = (const float*)d_in[8];
    const float* Ws1 = (const float*)d_in[9];
    const float* bs1 = (const float*)d_in[10];
    const float* g2  = (const float*)d_in[11];
    const float* be2 = (const float*)d_in[12];
    const float* Ws2 = (const float*)d_in[13];
    const float* bs2 = (const float*)d_in[14];
    const float* mix = (const float*)d_in[15];
    float* out = (float*)d_out;

    int N = in_sizes[0] / D;
    if (N > NMAX) N = NMAX;

    const int SMEM_K2 = (128 * LDSUB + 64 * LDW + 128 * LDA) * 4;
    const int SMEM_K3 = (2 * 128 * LDA + 128 * LDSUB + 64 * LDW + 5 * D + D) * 4;
    cudaFuncSetAttribute(k_bn1stats, cudaFuncAttributeMaxDynamicSharedMemorySize, SMEM_K2);
    cudaFuncSetAttribute(k_fused, cudaFuncAttributeMaxDynamicSharedMemorySize, SMEM_K3);

    int nb = (N + 127) / 128;
    k_zero<<<(G * D + 255) / 256, 256>>>();
    k_segstats<<<(N + 511) / 512, 128>>>(h, batch, N);
    k_bn1stats<<<nb, 256, SMEM_K2>>>(sub, W1, b1, N);
    k_gfin<<<(G * D + 255) / 256, 256>>>();
    k_bnfin1<<<1, 128>>>(g1, be1, 1.f / (float)N);
    k_fused<<<nb, 256, SMEM_K3>>>(h, sub, batch, W1, b1, Wg, bg, Ws1, bs1, N);
    k_bnfin2<<<1, 128>>>(g2, be2, 1.f / (float)N);
    k_score<<<nb, 128>>>(batch, Ws2, bs2, N);
    k_out<<<(G * D + 255) / 256, 256>>>(out, mix);
}

// round 3
// speedup vs baseline: 1.1704x; 1.1704x over previous
#include <cuda_runtime.h>
#include <math.h>

#define D 128
#define S 64
#define G 256
#define NMAX 400000

#define LDA 132      // fp32 A tiles: bank = 4*g4+t4, conflict-free
#define LDSUB 68     // sub tile:     bank = 4*g4+t4, conflict-free
#define LDW 136      // weight tiles: bank = 8*t4+g4, conflict-free (132 was 2-way!)

// ---------------- persistent device scratch (allocation-free) ----------------
__device__ float g_hfused[(size_t)NMAX * D];
__device__ float g_Z1[(size_t)NMAX * D];
__device__ float g_hs[G * D];
__device__ float g_hss[G * D];
__device__ float g_cnt[G];
__device__ float g_bn1sum[D], g_bn1sq[D];
__device__ float g_bn2sum[D], g_bn2sq[D];
__device__ float g_a1[D], g_c1[D], g_a2[D], g_c2[D];
__device__ float g_gm[G * D], g_gisd[G * D];
__device__ float g_num[G * D];
__device__ float g_den[G];

extern __shared__ float dynsmem[];

// ---------------- async copy helpers ----------------
__device__ __forceinline__ void cp16(void* dst_smem, const void* src) {
    unsigned a = (unsigned)__cvta_generic_to_shared(dst_smem);
    asm volatile("cp.async.cg.shared.global [%0], [%1], 16;\n" :: "r"(a), "l"(src));
}
__device__ __forceinline__ void cp_commit() { asm volatile("cp.async.commit_group;\n"); }
template <int NN> __device__ __forceinline__ void cp_wait() {
    asm volatile("cp.async.wait_group %0;\n" :: "n"(NN));
}

// ---------------- tf32 mma (raw fp32 bits: HW reads tf32 field only) ----------------
__device__ __forceinline__ void mma_tf32(float* d, unsigned a0, unsigned a1,
                                         unsigned a2, unsigned a3,
                                         unsigned b0, unsigned b1) {
    asm volatile(
        "mma.sync.aligned.m16n8k8.row.col.f32.tf32.tf32.f32 "
        "{%0,%1,%2,%3}, {%4,%5,%6,%7}, {%8,%9}, {%0,%1,%2,%3};\n"
        : "+f"(d[0]), "+f"(d[1]), "+f"(d[2]), "+f"(d[3])
        : "r"(a0), "r"(a1), "r"(a2), "r"(a3), "r"(b0), "r"(b1));
}

// 64-deep K chunk: warp computes 32x64 of a 128x128 tile. A fp32-bits smem, B fp32-bits smem.
__device__ __forceinline__ void warp_mma_chunk(float (&acc)[2][8][4],
                                               const unsigned* sA, int lda, int kcol0,
                                               const unsigned* sB,
                                               int wm, int wn, int lane) {
    int g4 = lane >> 2, t4 = lane & 3;
#pragma unroll
    for (int ks = 0; ks < 8; ks++) {
        int kk = ks * 8;
        unsigned a[2][4];
#pragma unroll
        for (int mt = 0; mt < 2; mt++) {
            const unsigned* p = sA + (wm * 32 + mt * 16 + g4) * lda + kcol0 + kk + t4;
            a[mt][0] = p[0];
            a[mt][1] = p[8 * lda];
            a[mt][2] = p[4];
            a[mt][3] = p[8 * lda + 4];
        }
#pragma unroll
        for (int nt = 0; nt < 8; nt++) {
            int nb = wn * 64 + nt * 8;
            unsigned b0 = sB[(kk + t4) * LDW + nb + g4];
            unsigned b1 = sB[(kk + 4 + t4) * LDW + nb + g4];
            mma_tf32(acc[0][nt], a[0][0], a[0][1], a[0][2], a[0][3], b0, b1);
            mma_tf32(acc[1][nt], a[1][0], a[1][1], a[1][2], a[1][3], b0, b1);
        }
    }
}

// 64x128 weight chunk -> smem buf (stride LDW), 256 threads, cp.async 16B
__device__ __forceinline__ void load_wchunk(float* buf, const float* Wsrc, int tid) {
#pragma unroll
    for (int j = 0; j < 8; j++) {
        int idx = tid + j * 256;
        int r = idx >> 5, c4 = idx & 31;
        cp16(buf + r * LDW + c4 * 4, Wsrc + r * 128 + c4 * 4);
    }
}

// ---------------- K0: zero accumulators ----------------
__global__ void k_zero() {
    int i = blockIdx.x * blockDim.x + threadIdx.x;
    if (i < G * D) { g_hs[i] = 0.f; g_hss[i] = 0.f; g_num[i] = 0.f; }
    if (i < G) { g_cnt[i] = 0.f; g_den[i] = 0.f; }
    if (i < D) { g_bn1sum[i] = 0.f; g_bn1sq[i] = 0.f; g_bn2sum[i] = 0.f; g_bn2sq[i] = 0.f; }
}

// ---------------- K1: merged h segment stats + BN1 stats of sub@W1+b1 ----------------
__global__ __launch_bounds__(256) void k_pass1(const float* __restrict__ h,
                                               const float* __restrict__ sub,
                                               const int* __restrict__ batch,
                                               const float* __restrict__ W1,
                                               const float* __restrict__ b1, int N) {
    float* Ss = dynsmem;                       // [128][LDSUB]
    float* Wb = Ss + 128 * LDSUB;              // [64][LDW]
    int* gid = (int*)(Wb + 64 * LDW);          // [128]
    int tid = threadIdx.x, lane = tid & 31, warp = tid >> 5;
    int wm = warp >> 1, wn = warp & 1;
    int r0 = blockIdx.x * 128;

    // async: sub tile + W1
#pragma unroll
    for (int j = 0; j < 8; j++) {
        int idx = tid + j * 256;
        int r = idx >> 4, c4 = idx & 15;
        int rr = min(r0 + r, N - 1);
        cp16(Ss + r * LDSUB + c4 * 4, sub + (size_t)rr * S + c4 * 4);
    }
    load_wchunk(Wb, W1, tid);
    cp_commit();

    if (tid < 128) gid[tid] = batch[min(r0 + tid, N - 1)];
    __syncthreads();

    // --- h segment stats (streamed, no smem) ---
    {
        int c = tid & 127, half = tid >> 7;
        int rbeg = half * 64;
        float s = 0.f, ss = 0.f, cf = 0.f;
        int cur = gid[rbeg];
        for (int i = 0; i < 64; i += 4) {
            float v[4];
#pragma unroll
            for (int j = 0; j < 4; j++) {
                int r = r0 + rbeg + i + j;
                v[j] = (r < N) ? h[(size_t)r * D + c] : 0.f;
            }
#pragma unroll
            for (int j = 0; j < 4; j++) {
                int rr = rbeg + i + j;
                int g = gid[rr];
                if (g != cur) {
                    atomicAdd(&g_hs[cur * D + c], s);
                    atomicAdd(&g_hss[cur * D + c], ss);
                    if (c == 0) atomicAdd(&g_cnt[cur], cf);
                    s = 0.f; ss = 0.f; cf = 0.f; cur = g;
                }
                if (r0 + rr < N) { s += v[j]; ss += v[j] * v[j]; cf += 1.f; }
            }
        }
        atomicAdd(&g_hs[cur * D + c], s);
        atomicAdd(&g_hss[cur * D + c], ss);
        if (c == 0) atomicAdd(&g_cnt[cur], cf);
    }

    // --- BN1 stats via mma, column-reduce straight from accumulators ---
    cp_wait<0>();
    __syncthreads();

    float acc[2][8][4];
#pragma unroll
    for (int mt = 0; mt < 2; mt++)
#pragma unroll
        for (int nt = 0; nt < 8; nt++)
#pragma unroll
            for (int e = 0; e < 4; e++) acc[mt][nt][e] = 0.f;

    warp_mma_chunk(acc, (const unsigned*)Ss, LDSUB, 0, (const unsigned*)Wb, wm, wn, lane);

    int g4 = lane >> 2, t4 = lane & 3;
#pragma unroll
    for (int nt = 0; nt < 8; nt++)
#pragma unroll
        for (int par = 0; par < 2; par++) {
            int ccol = wn * 64 + nt * 8 + t4 * 2 + par;
            float bb = b1[ccol];
            float s1 = 0.f, s2 = 0.f;
#pragma unroll
            for (int mt = 0; mt < 2; mt++)
#pragma unroll
                for (int rh = 0; rh < 2; rh++) {
                    int r = r0 + wm * 32 + mt * 16 + g4 + rh * 8;
                    float val = acc[mt][nt][rh * 2 + par] + bb;
                    if (r < N) { s1 += val; s2 += val * val; }
                }
#pragma unroll
            for (int o = 4; o < 32; o <<= 1) {
                s1 += __shfl_xor_sync(0xffffffffu, s1, o);
                s2 += __shfl_xor_sync(0xffffffffu, s2, o);
            }
            if (g4 == 0) {
                atomicAdd(&g_bn1sum[ccol], s1);
                atomicAdd(&g_bn1sq[ccol], s2);
            }
        }
}

// ---------------- K2: graph stat finalize + BN1 finalize (merged) ----------------
__global__ void k_mid(const float* __restrict__ gam, const float* __restrict__ bet, float invN) {
    int i = blockIdx.x * blockDim.x + threadIdx.x;
    if (i < G * D) {
        int g = i / D;
        float cnt = fmaxf(g_cnt[g], 1.f);
        float m = g_hs[i] / cnt;
        float v = g_hss[i] / cnt - m * m;
        float sd = sqrtf(fmaxf(v, 1e-8f));
        g_gm[i] = m;
        g_gisd[i] = 1.f / (sd + 1e-8f);
    }
    if (blockIdx.x == 0 && threadIdx.x < D) {
        int c = threadIdx.x;
        float mu = g_bn1sum[c] * invN;
        float var = g_bn1sq[c] * invN - mu * mu;
        float inv = rsqrtf(var + 1e-5f);
        g_a1[c] = gam[c] * inv;
        g_c1[c] = bet[c] - mu * gam[c] * inv;
    }
}

__global__ void k_bnfin2(const float* __restrict__ gam, const float* __restrict__ bet, float invN) {
    int i = threadIdx.x;
    float mu = g_bn2sum[i] * invN;
    float var = g_bn2sq[i] * invN - mu * mu;
    float inv = rsqrtf(var + 1e-5f);
    g_a2[i] = gam[i] * inv;
    g_c2[i] = bet[i] - mu * gam[i] * inv;
}

// ---------------- K3: big fused pass with double-buffered cp.async weights ----------------
__global__ __launch_bounds__(256, 1) void k_fused(
    const float* __restrict__ h, const float* __restrict__ sub, const int* __restrict__ batch,
    const float* __restrict__ W1, const float* __restrict__ b1,
    const float* __restrict__ Wg, const float* __restrict__ bg,
    const float* __restrict__ Ws1, const float* __restrict__ bs1, int N) {
    float* Hs = dynsmem;                          // [128][LDA]  h -> h_dev
    float* Es = Hs + 128 * LDA;                   // [128][LDA]  sub_e -> h_fused -> Z1
    float* Ss = Es + 128 * LDA;                   // [128][LDSUB] == [64][LDW] after mma1
    float* Wb = Ss + 128 * LDSUB;                 // [64][LDW]
    float* pa1 = Wb + 64 * LDW;
    float* pc1 = pa1 + D;
    float* pb1 = pc1 + D;
    float* pbg = pb1 + D;
    float* pbs1 = pbg + D;
    int* gid = (int*)(pbs1 + D);                  // [128]

    int tid = threadIdx.x, lane = tid & 31, warp = tid >> 5;
    int wm = warp >> 1, wn = warp & 1;
    int g4 = lane >> 2, t4 = lane & 3;
    int r0 = blockIdx.x * 128;

    // group1: Ss + Wb(W1); group2: Hs
#pragma unroll
    for (int j = 0; j < 8; j++) {
        int idx = tid + j * 256;
        int r = idx >> 4, c4 = idx & 15;
        int rr = min(r0 + r, N - 1);
        cp16(Ss + r * LDSUB + c4 * 4, sub + (size_t)rr * S + c4 * 4);
    }
    load_wchunk(Wb, W1, tid);
    cp_commit();
#pragma unroll
    for (int j = 0; j < 16; j++) {
        int idx = tid + j * 256;
        int r = idx >> 5, c4 = idx & 31;
        int rr = min(r0 + r, N - 1);
        cp16(Hs + r * LDA + c4 * 4, h + (size_t)rr * D + c4 * 4);
    }
    cp_commit();

    if (tid < 128) {
        pa1[tid] = g_a1[tid]; pc1[tid] = g_c1[tid]; pb1[tid] = b1[tid];
        pbg[tid] = bg[tid]; pbs1[tid] = bs1[tid];
        gid[tid] = batch[min(r0 + tid, N - 1)];
    }

    float acc[2][8][4];
#pragma unroll
    for (int mt = 0; mt < 2; mt++)
#pragma unroll
        for (int nt = 0; nt < 8; nt++)
#pragma unroll
            for (int e = 0; e < 4; e++) acc[mt][nt][e] = 0.f;

    // ---- mma1: X1 = sub @ W1 ----
    cp_wait<1>();            // Ss + Wb ready (Hs may still be in flight)
    __syncthreads();
    warp_mma_chunk(acc, (const unsigned*)Ss, LDSUB, 0, (const unsigned*)Wb, wm, wn, lane);

    // sub_e epilogue -> Es
#pragma unroll
    for (int mt = 0; mt < 2; mt++)
#pragma unroll
        for (int nt = 0; nt < 8; nt++)
#pragma unroll
            for (int e = 0; e < 4; e++) {
                int r = wm * 32 + mt * 16 + g4 + ((e >> 1) << 3);
                int c = wn * 64 + nt * 8 + t4 * 2 + (e & 1);
                float x = acc[mt][nt][e] + pb1[c];
                Es[r * LDA + c] = fmaxf(pa1[c] * x + pc1[c], 0.f);
                acc[mt][nt][e] = 0.f;
            }
    __syncthreads();         // Ss, Wb free; Es visible

    // prime the ping-pong: chunk0 -> Wb, chunk1 -> Ss
    const float* Wtab[8] = { Wg, Wg + 64 * D, Wg + 128 * D, Wg + 192 * D,
                             Ws1, Ws1 + 64 * D, Ws1 + 128 * D, Ws1 + 192 * D };
    load_wchunk(Wb, Wtab[0], tid); cp_commit();
    load_wchunk(Ss, Wtab[1], tid); cp_commit();

#pragma unroll 1
    for (int k = 0; k < 8; k++) {
        if (k < 6) cp_wait<1>(); else cp_wait<0>();
        __syncthreads();
        float* buf = (k & 1) ? Ss : Wb;
        // A operand: mma2 k0,k1 <- Hs(h), k2,k3 <- Es(sub_e); mma3 k4,k5 <- Es(h_fused), k6,k7 <- Hs(h_dev)
        const float* A = (k < 2) ? Hs : (k < 6) ? Es : Hs;
        warp_mma_chunk(acc, (const unsigned*)A, LDA, (k & 1) * 64, (const unsigned*)buf, wm, wn, lane);
        __syncthreads();
        if (k + 2 < 8) { load_wchunk(buf, Wtab[k + 2], tid); cp_commit(); }

        if (k == 3) {
            // gate epilogue -> Es = h_fused
#pragma unroll
            for (int mt = 0; mt < 2; mt++)
#pragma unroll
                for (int nt = 0; nt < 8; nt++)
#pragma unroll
                    for (int e = 0; e < 4; e++) {
                        int r = wm * 32 + mt * 16 + g4 + ((e >> 1) << 3);
                        int c = wn * 64 + nt * 8 + t4 * 2 + (e & 1);
                        float gx = acc[mt][nt][e] + pbg[c];
                        float gate = 1.f / (1.f + expf(-gx));
                        Es[r * LDA + c] = Hs[r * LDA + c] + gate * Es[r * LDA + c];
                        acc[mt][nt][e] = 0.f;
                    }
            __syncthreads();
            // write h_fused, transform Hs -> h_dev
            for (int i = tid; i < 128 * D; i += 256) {
                int r = i / D, c = i % D;
                if (r0 + r < N) g_hfused[(size_t)(r0 + r) * D + c] = Es[r * LDA + c];
                int g = gid[r];
                Hs[r * LDA + c] = (Hs[r * LDA + c] - g_gm[g * D + c]) * g_gisd[g * D + c];
            }
            __syncthreads();
        }
    }

    // Z1 epilogue -> Es
#pragma unroll
    for (int mt = 0; mt < 2; mt++)
#pragma unroll
        for (int nt = 0; nt < 8; nt++)
#pragma unroll
            for (int e = 0; e < 4; e++) {
                int r = wm * 32 + mt * 16 + g4 + ((e >> 1) << 3);
                int c = wn * 64 + nt * 8 + t4 * 2 + (e & 1);
                Es[r * LDA + c] = acc[mt][nt][e] + pbs1[c];
            }
    __syncthreads();

    // write Z1 + BN2 stats
    for (int i = tid; i < 128 * D; i += 256) {
        int r = i / D, c = i % D;
        if (r0 + r < N) g_Z1[(size_t)(r0 + r) * D + c] = Es[r * LDA + c];
    }
    {
        int c = tid & 127, half = tid >> 7;
        float s = 0.f, ss = 0.f;
        for (int r = half * 64; r < half * 64 + 64; r++) {
            if (r0 + r < N) {
                float v = Es[r * LDA + c];
                s += v; ss += v * v;
            }
        }
        atomicAdd(&g_bn2sum[c], s);
        atomicAdd(&g_bn2sq[c], ss);
    }
}

// ---------------- K5: logits + exp (shift-invariant) + weighted segment sums ----------------
__global__ __launch_bounds__(256) void k_score(const int* __restrict__ batch,
                                               const float* __restrict__ Ws2,
                                               const float* __restrict__ bs2, int N) {
    __shared__ float es[256];
    __shared__ int gid[256];
    int tid = threadIdx.x, lane = tid & 31, warp = tid >> 5;
    int r0 = blockIdx.x * 256;
    int nr = min(256, N - r0);
    gid[tid] = batch[min(r0 + min(tid, nr - 1), N - 1)];

    float a2v[4], c2v[4], wv[4];
#pragma unroll
    for (int j = 0; j < 4; j++) {
        int c = lane + 32 * j;
        a2v[j] = g_a2[c]; c2v[j] = g_c2[c]; wv[j] = Ws2[c];
    }
    float bsv = bs2[0];

    // phase 1: warp-per-row logits (8 warps x 32 rows)
    int rbase = warp * 32;
    for (int rr = rbase; rr < rbase + 32; rr++) {
        if (rr >= nr) { if (lane == 0) es[rr] = 0.f; continue; }
        const float* z = g_Z1 + (size_t)(r0 + rr) * D;
        float p = 0.f;
#pragma unroll
        for (int j = 0; j < 4; j++) {
            float zz = z[lane + 32 * j];
            p += fmaxf(a2v[j] * zz + c2v[j], 0.f) * wv[j];
        }
#pragma unroll
        for (int o = 16; o > 0; o >>= 1) p += __shfl_xor_sync(0xffffffffu, p, o);
        if (lane == 0) es[rr] = expf(p + bsv);
    }
    __syncthreads();

    // phase 2: column-owner weighted segment sums (2 halves x 128 rows)
    int c = tid & 127, half = tid >> 7;
    int rb = half * 128;
    float accn = 0.f, accd = 0.f;
    int cur = gid[rb];
    for (int i = 0; i < 128; i += 4) {
        float v[4], e[4];
#pragma unroll
        for (int j = 0; j < 4; j++) {
            int rr = rb + i + j;
            int r = r0 + rr;
            v[j] = (r < N) ? g_hfused[(size_t)r * D + c] : 0.f;
            e[j] = es[rr];
        }
#pragma unroll
        for (int j = 0; j < 4; j++) {
            int rr = rb + i + j;
            int g = gid[rr];
            if (g != cur) {
                atomicAdd(&g_num[cur * D + c], accn);
                if (c == 0) atomicAdd(&g_den[cur], accd);
                accn = 0.f; accd = 0.f; cur = g;
            }
            if (r0 + rr < N) { accn += e[j] * v[j]; accd += e[j]; }
        }
    }
    atomicAdd(&g_num[cur * D + c], accn);
    if (c == 0) atomicAdd(&g_den[cur], accd);
}

// ---------------- K6: final combine ----------------
__global__ void k_out(float* __restrict__ out, const float* __restrict__ mix) {
    int i = blockIdx.x * blockDim.x + threadIdx.x;
    if (i >= G * D) return;
    int g = i / D;
    float alpha = 1.f / (1.f + expf(-mix[0]));
    float den = g_den[g];
    float wf = (den > 0.f) ? (g_num[i] / den) : 0.f;
    out[i] = alpha * wf + (1.f - alpha) * g_gm[i];
}

// ---------------- launch ----------------
extern "C" void kernel_launch(void* const* d_in, const int* in_sizes, int n_in,
                              void* d_out, int out_size) {
    const float* h   = (const float*)d_in[0];
    const float* sub = (const float*)d_in[1];
    const int* batch = (const int*)d_in[2];
    const float* W1  = (const float*)d_in[3];
    const float* b1  = (const float*)d_in[4];
    const float* g1  = (const float*)d_in[5];
    const float* be1 = (const float*)d_in[6];
    const float* Wg  = (const float*)d_in[7];
    const float* bg  = (const float*)d_in[8];
    const float* Ws1 = (const float*)d_in[9];
    const float* bs1 = (const float*)d_in[10];
    const float* g2  = (const float*)d_in[11];
    const float* be2 = (const float*)d_in[12];
    const float* Ws2 = (const float*)d_in[13];
    const float* bs2 = (const float*)d_in[14];
    const float* mix = (const float*)d_in[15];
    float* out = (float*)d_out;

    int N = in_sizes[0] / D;
    if (N > NMAX) N = NMAX;

    const int SMEM_P1 = (128 * LDSUB + 64 * LDW + 128) * 4;
    const int SMEM_K3 = (2 * 128 * LDA + 128 * LDSUB + 64 * LDW + 5 * D + D) * 4;
    cudaFuncSetAttribute(k_pass1, cudaFuncAttributeMaxDynamicSharedMemorySize, SMEM_P1);
    cudaFuncSetAttribute(k_fused, cudaFuncAttributeMaxDynamicSharedMemorySize, SMEM_K3);

    int nb = (N + 127) / 128;
    int nb2 = (N + 255) / 256;
    k_zero<<<(G * D + 255) / 256, 256>>>();
    k_pass1<<<nb, 256, SMEM_P1>>>(h, sub, batch, W1, b1, N);
    k_mid<<<(G * D + 255) / 256, 256>>>(g1, be1, 1.f / (float)N);
    k_fused<<<nb, 256, SMEM_K3>>>(h, sub, batch, W1, b1, Wg, bg, Ws1, bs1, N);
    k_bnfin2<<<1, 128>>>(g2, be2, 1.f / (float)N);
    k_score<<<nb2, 256>>>(batch, Ws2, bs2, N);
    k_out<<<(G * D + 255) / 256, 256>>>(out, mix);
}

// round 4
// speedup vs baseline: 1.7179x; 1.4678x over previous
#include <cuda_runtime.h>
#include <math.h>

#define D 128
#define S 64
#define G 256
#define NMAX 400000

#define LDA 132      // fp32 A tiles: bank = 4*g4+t4, conflict-free
#define LDSUB 68     // sub tile:     bank = 4*g4+t4, conflict-free
#define LDW 136      // weight tiles: bank = 8*t4+g4, conflict-free

#define NT 512       // threads for the mma kernels (16 warps)

// ---------------- persistent device scratch (allocation-free) ----------------
__device__ float g_hfused[(size_t)NMAX * D];
__device__ float g_Z1[(size_t)NMAX * D];
__device__ float g_hs[G * D];
__device__ float g_hss[G * D];
__device__ float g_cnt[G];
__device__ float g_bn1sum[D], g_bn1sq[D];
__device__ float g_bn2sum[D], g_bn2sq[D];
__device__ float g_a1[D], g_c1[D], g_a2[D], g_c2[D];
__device__ float g_gm[G * D], g_gisd[G * D];
__device__ float g_num[G * D];
__device__ float g_den[G];

extern __shared__ float dynsmem[];

// ---------------- async copy helpers ----------------
__device__ __forceinline__ void cp16(void* dst_smem, const void* src) {
    unsigned a = (unsigned)__cvta_generic_to_shared(dst_smem);
    asm volatile("cp.async.cg.shared.global [%0], [%1], 16;\n" :: "r"(a), "l"(src));
}
__device__ __forceinline__ void cp_commit() { asm volatile("cp.async.commit_group;\n"); }
template <int NN> __device__ __forceinline__ void cp_wait() {
    asm volatile("cp.async.wait_group %0;\n" :: "n"(NN));
}

// ---------------- tf32 mma (raw fp32 bits: HW reads tf32 field only) ----------------
__device__ __forceinline__ void mma_tf32(float* d, unsigned a0, unsigned a1,
                                         unsigned a2, unsigned a3,
                                         unsigned b0, unsigned b1) {
    asm volatile(
        "mma.sync.aligned.m16n8k8.row.col.f32.tf32.tf32.f32 "
        "{%0,%1,%2,%3}, {%4,%5,%6,%7}, {%8,%9}, {%0,%1,%2,%3};\n"
        : "+f"(d[0]), "+f"(d[1]), "+f"(d[2]), "+f"(d[3])
        : "r"(a0), "r"(a1), "r"(a2), "r"(a3), "r"(b0), "r"(b1));
}

// 64-deep K chunk: warp computes a 32x32 sub-tile of a 128x128 block tile.
// 16 warps: wm = warp>>2 (M), wn = warp&3 (N).
__device__ __forceinline__ void warp_mma_chunk(float (&acc)[2][4][4],
                                               const unsigned* sA, int lda, int kcol0,
                                               const unsigned* sB,
                                               int wm, int wn, int lane) {
    int g4 = lane >> 2, t4 = lane & 3;
#pragma unroll
    for (int ks = 0; ks < 8; ks++) {
        int kk = ks * 8;
        unsigned a[2][4];
#pragma unroll
        for (int mt = 0; mt < 2; mt++) {
            const unsigned* p = sA + (wm * 32 + mt * 16 + g4) * lda + kcol0 + kk + t4;
            a[mt][0] = p[0];
            a[mt][1] = p[8 * lda];
            a[mt][2] = p[4];
            a[mt][3] = p[8 * lda + 4];
        }
#pragma unroll
        for (int nt = 0; nt < 4; nt++) {
            int nb = wn * 32 + nt * 8;
            unsigned b0 = sB[(kk + t4) * LDW + nb + g4];
            unsigned b1 = sB[(kk + 4 + t4) * LDW + nb + g4];
            mma_tf32(acc[0][nt], a[0][0], a[0][1], a[0][2], a[0][3], b0, b1);
            mma_tf32(acc[1][nt], a[1][0], a[1][1], a[1][2], a[1][3], b0, b1);
        }
    }
}

// 64x128 weight chunk -> smem (stride LDW), NT threads, cp.async 16B
__device__ __forceinline__ void load_wchunk(float* buf, const float* Wsrc, int tid) {
#pragma unroll
    for (int j = 0; j < 4; j++) {
        int idx = tid + j * NT;
        int r = idx >> 5, c4 = idx & 31;
        cp16(buf + r * LDW + c4 * 4, Wsrc + r * 128 + c4 * 4);
    }
}

// ---------------- K0: zero accumulators ----------------
__global__ void k_zero() {
    int i = blockIdx.x * blockDim.x + threadIdx.x;
    if (i < G * D) { g_hs[i] = 0.f; g_hss[i] = 0.f; g_num[i] = 0.f; }
    if (i < G) { g_cnt[i] = 0.f; g_den[i] = 0.f; }
    if (i < D) { g_bn1sum[i] = 0.f; g_bn1sq[i] = 0.f; g_bn2sum[i] = 0.f; g_bn2sq[i] = 0.f; }
}

// ---------------- K1: merged h segment stats + BN1 stats of sub@W1+b1 ----------------
__global__ __launch_bounds__(NT) void k_pass1(const float* __restrict__ h,
                                              const float* __restrict__ sub,
                                              const int* __restrict__ batch,
                                              const float* __restrict__ W1,
                                              const float* __restrict__ b1, int N) {
    float* Ss = dynsmem;                       // [128][LDSUB]
    float* Wb = Ss + 128 * LDSUB;              // [64][LDW]
    int* gid = (int*)(Wb + 64 * LDW);          // [128]
    int tid = threadIdx.x, lane = tid & 31, warp = tid >> 5;
    int wm = warp >> 2, wn = warp & 3;
    int r0 = blockIdx.x * 128;

    // async: sub tile + W1
#pragma unroll
    for (int j = 0; j < 4; j++) {
        int idx = tid + j * NT;
        int r = idx >> 4, c4 = idx & 15;
        int rr = min(r0 + r, N - 1);
        cp16(Ss + r * LDSUB + c4 * 4, sub + (size_t)rr * S + c4 * 4);
    }
    load_wchunk(Wb, W1, tid);
    cp_commit();

    if (tid < 128) gid[tid] = batch[min(r0 + tid, N - 1)];
    __syncthreads();

    // --- h segment stats (streamed, no smem): 4 quarters x 32 rows ---
    {
        int c = tid & 127, q = tid >> 7;
        int rbeg = q * 32;
        float s = 0.f, ss = 0.f, cf = 0.f;
        int cur = gid[rbeg];
        for (int i = 0; i < 32; i += 4) {
            float v[4];
#pragma unroll
            for (int j = 0; j < 4; j++) {
                int r = r0 + rbeg + i + j;
                v[j] = (r < N) ? h[(size_t)r * D + c] : 0.f;
            }
#pragma unroll
            for (int j = 0; j < 4; j++) {
                int rr = rbeg + i + j;
                int g = gid[rr];
                if (g != cur) {
                    atomicAdd(&g_hs[cur * D + c], s);
                    atomicAdd(&g_hss[cur * D + c], ss);
                    if (c == 0) atomicAdd(&g_cnt[cur], cf);
                    s = 0.f; ss = 0.f; cf = 0.f; cur = g;
                }
                if (r0 + rr < N) { s += v[j]; ss += v[j] * v[j]; cf += 1.f; }
            }
        }
        atomicAdd(&g_hs[cur * D + c], s);
        atomicAdd(&g_hss[cur * D + c], ss);
        if (c == 0) atomicAdd(&g_cnt[cur], cf);
    }

    // --- BN1 stats via mma, column-reduce straight from accumulators ---
    cp_wait<0>();
    __syncthreads();

    float acc[2][4][4];
#pragma unroll
    for (int mt = 0; mt < 2; mt++)
#pragma unroll
        for (int nt = 0; nt < 4; nt++)
#pragma unroll
            for (int e = 0; e < 4; e++) acc[mt][nt][e] = 0.f;

    warp_mma_chunk(acc, (const unsigned*)Ss, LDSUB, 0, (const unsigned*)Wb, wm, wn, lane);

    int g4 = lane >> 2, t4 = lane & 3;
#pragma unroll
    for (int nt = 0; nt < 4; nt++)
#pragma unroll
        for (int par = 0; par < 2; par++) {
            int ccol = wn * 32 + nt * 8 + t4 * 2 + par;
            float bb = b1[ccol];
            float s1 = 0.f, s2 = 0.f;
#pragma unroll
            for (int mt = 0; mt < 2; mt++)
#pragma unroll
                for (int rh = 0; rh < 2; rh++) {
                    int r = r0 + wm * 32 + mt * 16 + g4 + rh * 8;
                    float val = acc[mt][nt][rh * 2 + par] + bb;
                    if (r < N) { s1 += val; s2 += val * val; }
                }
#pragma unroll
            for (int o = 4; o < 32; o <<= 1) {
                s1 += __shfl_xor_sync(0xffffffffu, s1, o);
                s2 += __shfl_xor_sync(0xffffffffu, s2, o);
            }
            if (g4 == 0) {
                atomicAdd(&g_bn1sum[ccol], s1);
                atomicAdd(&g_bn1sq[ccol], s2);
            }
        }
}

// ---------------- K2: graph stat finalize + BN1 finalize (merged) ----------------
__global__ void k_mid(const float* __restrict__ gam, const float* __restrict__ bet, float invN) {
    int i = blockIdx.x * blockDim.x + threadIdx.x;
    if (i < G * D) {
        int g = i / D;
        float cnt = fmaxf(g_cnt[g], 1.f);
        float m = g_hs[i] / cnt;
        float v = g_hss[i] / cnt - m * m;
        float sd = sqrtf(fmaxf(v, 1e-8f));
        g_gm[i] = m;
        g_gisd[i] = 1.f / (sd + 1e-8f);
    }
    if (blockIdx.x == 0 && threadIdx.x < D) {
        int c = threadIdx.x;
        float mu = g_bn1sum[c] * invN;
        float var = g_bn1sq[c] * invN - mu * mu;
        float inv = rsqrtf(var + 1e-5f);
        g_a1[c] = gam[c] * inv;
        g_c1[c] = bet[c] - mu * gam[c] * inv;
    }
}

__global__ void k_bnfin2(const float* __restrict__ gam, const float* __restrict__ bet, float invN) {
    int i = threadIdx.x;
    float mu = g_bn2sum[i] * invN;
    float var = g_bn2sq[i] * invN - mu * mu;
    float inv = rsqrtf(var + 1e-5f);
    g_a2[i] = gam[i] * inv;
    g_c2[i] = bet[i] - mu * gam[i] * inv;
}

// ---------------- K3: big fused pass, 512 threads, warp tile 32x32 ----------------
__global__ __launch_bounds__(NT, 1) void k_fused(
    const float* __restrict__ h, const float* __restrict__ sub, const int* __restrict__ batch,
    const float* __restrict__ W1, const float* __restrict__ b1,
    const float* __restrict__ Wg, const float* __restrict__ bg,
    const float* __restrict__ Ws1, const float* __restrict__ bs1, int N) {
    float* Hs = dynsmem;                          // [128][LDA]  h -> h_dev
    float* Es = Hs + 128 * LDA;                   // [128][LDA]  sub_e -> h_fused -> Z1
    float* Ss = Es + 128 * LDA;                   // [128][LDSUB] == ping buffer after mma1
    float* Wb = Ss + 128 * LDSUB;                 // [64][LDW]    pong buffer
    float* pa1 = Wb + 64 * LDW;
    float* pc1 = pa1 + D;
    float* pb1 = pc1 + D;
    float* pbg = pb1 + D;
    float* pbs1 = pbg + D;
    int* gid = (int*)(pbs1 + D);                  // [128]

    int tid = threadIdx.x, lane = tid & 31, warp = tid >> 5;
    int wm = warp >> 2, wn = warp & 3;
    int g4 = lane >> 2, t4 = lane & 3;
    int r0 = blockIdx.x * 128;

    // group1: Ss + Wb(W1); group2: Hs
#pragma unroll
    for (int j = 0; j < 4; j++) {
        int idx = tid + j * NT;
        int r = idx >> 4, c4 = idx & 15;
        int rr = min(r0 + r, N - 1);
        cp16(Ss + r * LDSUB + c4 * 4, sub + (size_t)rr * S + c4 * 4);
    }
    load_wchunk(Wb, W1, tid);
    cp_commit();
#pragma unroll
    for (int j = 0; j < 8; j++) {
        int idx = tid + j * NT;
        int r = idx >> 5, c4 = idx & 31;
        int rr = min(r0 + r, N - 1);
        cp16(Hs + r * LDA + c4 * 4, h + (size_t)rr * D + c4 * 4);
    }
    cp_commit();

    if (tid < 128) {
        pa1[tid] = g_a1[tid]; pc1[tid] = g_c1[tid]; pb1[tid] = b1[tid];
        pbg[tid] = bg[tid]; pbs1[tid] = bs1[tid];
        gid[tid] = batch[min(r0 + tid, N - 1)];
    }

    float acc[2][4][4];
#pragma unroll
    for (int mt = 0; mt < 2; mt++)
#pragma unroll
        for (int nt = 0; nt < 4; nt++)
#pragma unroll
            for (int e = 0; e < 4; e++) acc[mt][nt][e] = 0.f;

    // ---- mma1: X1 = sub @ W1 ----
    cp_wait<1>();            // Ss + Wb ready (Hs may still be in flight)
    __syncthreads();
    warp_mma_chunk(acc, (const unsigned*)Ss, LDSUB, 0, (const unsigned*)Wb, wm, wn, lane);

    // sub_e epilogue -> Es
#pragma unroll
    for (int mt = 0; mt < 2; mt++)
#pragma unroll
        for (int nt = 0; nt < 4; nt++)
#pragma unroll
            for (int e = 0; e < 4; e++) {
                int r = wm * 32 + mt * 16 + g4 + ((e >> 1) << 3);
                int c = wn * 32 + nt * 8 + t4 * 2 + (e & 1);
                float x = acc[mt][nt][e] + pb1[c];
                Es[r * LDA + c] = fmaxf(pa1[c] * x + pc1[c], 0.f);
                acc[mt][nt][e] = 0.f;
            }
    __syncthreads();         // Ss, Wb free; Es visible

    // prime the ping-pong: chunk0 -> Wb, chunk1 -> Ss
    const float* Wtab[8] = { Wg, Wg + 64 * D, Wg + 128 * D, Wg + 192 * D,
                             Ws1, Ws1 + 64 * D, Ws1 + 128 * D, Ws1 + 192 * D };
    load_wchunk(Wb, Wtab[0], tid); cp_commit();
    load_wchunk(Ss, Wtab[1], tid); cp_commit();

#pragma unroll 1
    for (int k = 0; k < 8; k++) {
        if (k < 6) cp_wait<1>(); else cp_wait<0>();
        __syncthreads();
        float* buf = (k & 1) ? Ss : Wb;
        // A: mma2 k0,k1 <- Hs(h), k2,k3 <- Es(sub_e); mma3 k4,k5 <- Es(h_fused), k6,k7 <- Hs(h_dev)
        const float* A = (k < 2) ? Hs : (k < 6) ? Es : Hs;
        warp_mma_chunk(acc, (const unsigned*)A, LDA, (k & 1) * 64, (const unsigned*)buf, wm, wn, lane);
        __syncthreads();
        if (k + 2 < 8) { load_wchunk(buf, Wtab[k + 2], tid); cp_commit(); }

        if (k == 3) {
            // gate epilogue -> Es = h_fused
#pragma unroll
            for (int mt = 0; mt < 2; mt++)
#pragma unroll
                for (int nt = 0; nt < 4; nt++)
#pragma unroll
                    for (int e = 0; e < 4; e++) {
                        int r = wm * 32 + mt * 16 + g4 + ((e >> 1) << 3);
                        int c = wn * 32 + nt * 8 + t4 * 2 + (e & 1);
                        float gx = acc[mt][nt][e] + pbg[c];
                        float gate = 1.f / (1.f + expf(-gx));
                        Es[r * LDA + c] = Hs[r * LDA + c] + gate * Es[r * LDA + c];
                        acc[mt][nt][e] = 0.f;
                    }
            __syncthreads();
            // write h_fused, transform Hs -> h_dev
            for (int i = tid; i < 128 * D; i += NT) {
                int r = i >> 7, c = i & 127;
                if (r0 + r < N) g_hfused[(size_t)(r0 + r) * D + c] = Es[r * LDA + c];
                int g = gid[r];
                Hs[r * LDA + c] = (Hs[r * LDA + c] - g_gm[g * D + c]) * g_gisd[g * D + c];
            }
            __syncthreads();
        }
    }

    // Z1 epilogue -> Es
#pragma unroll
    for (int mt = 0; mt < 2; mt++)
#pragma unroll
        for (int nt = 0; nt < 4; nt++)
#pragma unroll
            for (int e = 0; e < 4; e++) {
                int r = wm * 32 + mt * 16 + g4 + ((e >> 1) << 3);
                int c = wn * 32 + nt * 8 + t4 * 2 + (e & 1);
                Es[r * LDA + c] = acc[mt][nt][e] + pbs1[c];
            }
    __syncthreads();

    // write Z1 + BN2 stats (4 quarters x 32 rows)
    for (int i = tid; i < 128 * D; i += NT) {
        int r = i >> 7, c = i & 127;
        if (r0 + r < N) g_Z1[(size_t)(r0 + r) * D + c] = Es[r * LDA + c];
    }
    {
        int c = tid & 127, q = tid >> 7;
        float s = 0.f, ss = 0.f;
        for (int r = q * 32; r < q * 32 + 32; r++) {
            if (r0 + r < N) {
                float v = Es[r * LDA + c];
                s += v; ss += v * v;
            }
        }
        atomicAdd(&g_bn2sum[c], s);
        atomicAdd(&g_bn2sq[c], ss);
    }
}

// ---------------- K5: logits + exp (shift-invariant) + weighted segment sums ----------------
__global__ __launch_bounds__(256) void k_score(const int* __restrict__ batch,
                                               const float* __restrict__ Ws2,
                                               const float* __restrict__ bs2, int N) {
    __shared__ float es[256];
    __shared__ int gid[256];
    int tid = threadIdx.x, lane = tid & 31, warp = tid >> 5;
    int r0 = blockIdx.x * 256;
    int nr = min(256, N - r0);
    gid[tid] = batch[min(r0 + min(tid, nr - 1), N - 1)];

    float a2v[4], c2v[4], wv[4];
#pragma unroll
    for (int j = 0; j < 4; j++) {
        int c = lane + 32 * j;
        a2v[j] = g_a2[c]; c2v[j] = g_c2[c]; wv[j] = Ws2[c];
    }
    float bsv = bs2[0];

    // phase 1: warp-per-row logits (8 warps x 32 rows)
    int rbase = warp * 32;
    for (int rr = rbase; rr < rbase + 32; rr++) {
        if (rr >= nr) { if (lane == 0) es[rr] = 0.f; continue; }
        const float* z = g_Z1 + (size_t)(r0 + rr) * D;
        float p = 0.f;
#pragma unroll
        for (int j = 0; j < 4; j++) {
            float zz = z[lane + 32 * j];
            p += fmaxf(a2v[j] * zz + c2v[j], 0.f) * wv[j];
        }
#pragma unroll
        for (int o = 16; o > 0; o >>= 1) p += __shfl_xor_sync(0xffffffffu, p, o);
        if (lane == 0) es[rr] = expf(p + bsv);
    }
    __syncthreads();

    // phase 2: column-owner weighted segment sums (2 halves x 128 rows)
    int c = tid & 127, half = tid >> 7;
    int rb = half * 128;
    float accn = 0.f, accd = 0.f;
    int cur = gid[rb];
    for (int i = 0; i < 128; i += 4) {
        float v[4], e[4];
#pragma unroll
        for (int j = 0; j < 4; j++) {
            int rr = rb + i + j;
            int r = r0 + rr;
            v[j] = (r < N) ? g_hfused[(size_t)r * D + c] : 0.f;
            e[j] = es[rr];
        }
#pragma unroll
        for (int j = 0; j < 4; j++) {
            int rr = rb + i + j;
            int g = gid[rr];
            if (g != cur) {
                atomicAdd(&g_num[cur * D + c], accn);
                if (c == 0) atomicAdd(&g_den[cur], accd);
                accn = 0.f; accd = 0.f; cur = g;
            }
            if (r0 + rr < N) { accn += e[j] * v[j]; accd += e[j]; }
        }
    }
    atomicAdd(&g_num[cur * D + c], accn);
    if (c == 0) atomicAdd(&g_den[cur], accd);
}

// ---------------- K6: final combine ----------------
__global__ void k_out(float* __restrict__ out, const float* __restrict__ mix) {
    int i = blockIdx.x * blockDim.x + threadIdx.x;
    if (i >= G * D) return;
    int g = i / D;
    float alpha = 1.f / (1.f + expf(-mix[0]));
    float den = g_den[g];
    float wf = (den > 0.f) ? (g_num[i] / den) : 0.f;
    out[i] = alpha * wf + (1.f - alpha) * g_gm[i];
}

// ---------------- launch ----------------
extern "C" void kernel_launch(void* const* d_in, const int* in_sizes, int n_in,
                              void* d_out, int out_size) {
    const float* h   = (const float*)d_in[0];
    const float* sub = (const float*)d_in[1];
    const int* batch = (const int*)d_in[2];
    const float* W1  = (const float*)d_in[3];
    const float* b1  = (const float*)d_in[4];
    const float* g1  = (const float*)d_in[5];
    const float* be1 = (const float*)d_in[6];
    const float* Wg  = (const float*)d_in[7];
    const float* bg  = (const float*)d_in[8];
    const float* Ws1 = (const float*)d_in[9];
    const float* bs1 = (const float*)d_in[10];
    const float* g2  = (const float*)d_in[11];
    const float* be2 = (const float*)d_in[12];
    const float* Ws2 = (const float*)d_in[13];
    const float* bs2 = (const float*)d_in[14];
    const float* mix = (const float*)d_in[15];
    float* out = (float*)d_out;

    int N = in_sizes[0] / D;
    if (N > NMAX) N = NMAX;

    const int SMEM_P1 = (128 * LDSUB + 64 * LDW + 128) * 4;
    const int SMEM_K3 = (2 * 128 * LDA + 128 * LDSUB + 64 * LDW + 5 * D + D) * 4;
    cudaFuncSetAttribute(k_pass1, cudaFuncAttributeMaxDynamicSharedMemorySize, SMEM_P1);
    cudaFuncSetAttribute(k_fused, cudaFuncAttributeMaxDynamicSharedMemorySize, SMEM_K3);

    int nb = (N + 127) / 128;
    int nb2 = (N + 255) / 256;
    k_zero<<<(G * D + 255) / 256, 256>>>();
    k_pass1<<<nb, NT, SMEM_P1>>>(h, sub, batch, W1, b1, N);
    k_mid<<<(G * D + 255) / 256, 256>>>(g1, be1, 1.f / (float)N);
    k_fused<<<nb, NT, SMEM_K3>>>(h, sub, batch, W1, b1, Wg, bg, Ws1, bs1, N);
    k_bnfin2<<<1, 128>>>(g2, be2, 1.f / (float)N);
    k_score<<<nb2, 256>>>(batch, Ws2, bs2, N);
    k_out<<<(G * D + 255) / 256, 256>>>(out, mix);
}

// round 7
// speedup vs baseline: 2.1875x; 1.2734x over previous
#include <cuda_runtime.h>
#include <cuda_bf16.h>
#include <math.h>

#define D 128
#define S 64
#define G 256
#define NMAX 400000

#define LDH 136    // bf16 stride, activation tiles: bank = 4*g4+t4, conflict-free
#define LDWB 72    // bf16 stride, [n][k] weight tiles + sub tile: bank = 4*g4+t4
#define NT 256

typedef __nv_bfloat16 bf16;

// ---------------- persistent device scratch (allocation-free) ----------------
__device__ bf16 g_hb[(size_t)NMAX * D];
__device__ bf16 g_subb[(size_t)NMAX * S];
__device__ bf16 g_W1b[D * S];          // [n=128][k=64] transposed
__device__ bf16 g_Wgb[4 * D * S];      // [ck][n][k]
__device__ bf16 g_Ws1b[4 * D * S];     // [ck][n][k]
__device__ float g_hfused[(size_t)NMAX * D];
__device__ float g_Z1[(size_t)NMAX * D];
__device__ float g_hs[G * D];
__device__ float g_hss[G * D];
__device__ float g_cnt[G];
__device__ float g_bn1sum[D], g_bn1sq[D];
__device__ float g_bn2sum[D], g_bn2sq[D];
__device__ float g_a1[D], g_c1[D], g_a2[D], g_c2[D];
__device__ float g_gm[G * D], g_gisd[G * D];
__device__ float g_num[G * D];
__device__ float g_den[G];

extern __shared__ float dynsmem[];

// ---------------- helpers ----------------
__device__ __forceinline__ void cp16(void* dst_smem, const void* src) {
    unsigned a = (unsigned)__cvta_generic_to_shared(dst_smem);
    asm volatile("cp.async.cg.shared.global [%0], [%1], 16;\n" :: "r"(a), "l"(src));
}
__device__ __forceinline__ void cp_commit() { asm volatile("cp.async.commit_group;\n"); }
template <int NN> __device__ __forceinline__ void cp_wait() {
    asm volatile("cp.async.wait_group %0;\n" :: "n"(NN));
}

__device__ __forceinline__ unsigned pk(float lo, float hi) {
    unsigned r;
    asm("cvt.rn.bf16x2.f32 %0, %1, %2;" : "=r"(r) : "f"(hi), "f"(lo));
    return r;
}
__device__ __forceinline__ void upk(unsigned v, float& lo, float& hi) {
    lo = __uint_as_float(v << 16);
    hi = __uint_as_float(v & 0xffff0000u);
}

__device__ __forceinline__ void mma_bf16(float* d, const unsigned* a, unsigned b0, unsigned b1) {
    asm volatile(
        "mma.sync.aligned.m16n8k16.row.col.f32.bf16.bf16.f32 "
        "{%0,%1,%2,%3}, {%4,%5,%6,%7}, {%8,%9}, {%0,%1,%2,%3};\n"
        : "+f"(d[0]), "+f"(d[1]), "+f"(d[2]), "+f"(d[3])
        : "r"(a[0]), "r"(a[1]), "r"(a[2]), "r"(a[3]), "r"(b0), "r"(b1));
}

// 64-deep K chunk; warp computes a 32(M)x64(N) sub-tile of a 128x128 block tile.
// 8 warps: wm = warp>>1 (0..3), wn = warp&1 (0..1).
// sA: bf16 [128][lda]; sB: bf16 weight tile [n=128][k=64] stride LDWB.
__device__ __forceinline__ void mma_chunk(float (&acc)[2][8][4],
                                          const bf16* sA, int lda, int kcol0,
                                          const bf16* sB, int wm, int wn, int lane) {
    int g4 = lane >> 2, t4 = lane & 3;
#pragma unroll
    for (int ks = 0; ks < 4; ks++) {
        int kk = ks * 16;
        unsigned a[2][4];
#pragma unroll
        for (int mt = 0; mt < 2; mt++) {
            const bf16* p = sA + (wm * 32 + mt * 16 + g4) * lda + kcol0 + kk + 2 * t4;
            a[mt][0] = *(const unsigned*)p;
            a[mt][1] = *(const unsigned*)(p + 8 * lda);
            a[mt][2] = *(const unsigned*)(p + 8);
            a[mt][3] = *(const unsigned*)(p + 8 * lda + 8);
        }
#pragma unroll
        for (int nt = 0; nt < 8; nt++) {
            const bf16* q = sB + (wn * 64 + nt * 8 + g4) * LDWB + kk + 2 * t4;
            unsigned b0 = *(const unsigned*)q;
            unsigned b1 = *(const unsigned*)(q + 8);
            mma_bf16(acc[0][nt], a[0], b0, b1);
            mma_bf16(acc[1][nt], a[1], b0, b1);
        }
    }
}

// bf16 weight chunk [128][64] global -> smem [128][LDWB]
__device__ __forceinline__ void load_wchunk(bf16* buf, const bf16* Wsrc, int tid) {
#pragma unroll
    for (int j = 0; j < 4; j++) {
        int idx = tid + j * NT;
        int n = idx >> 3, f = idx & 7;
        cp16(buf + n * LDWB + f * 8, Wsrc + n * 64 + f * 8);
    }
}

// ---------------- K0: zero accumulators ----------------
__global__ void k_zero() {
    int i = blockIdx.x * blockDim.x + threadIdx.x;
    if (i < G * D) { g_hs[i] = 0.f; g_hss[i] = 0.f; g_num[i] = 0.f; }
    if (i < G) { g_cnt[i] = 0.f; g_den[i] = 0.f; }
    if (i < D) { g_bn1sum[i] = 0.f; g_bn1sq[i] = 0.f; g_bn2sum[i] = 0.f; g_bn2sq[i] = 0.f; }
}

// ---------------- K-prep: weights -> bf16, transposed [n][k] chunks ----------------
__global__ void k_prep(const float* __restrict__ W1, const float* __restrict__ Wg,
                       const float* __restrict__ Ws1) {
    int i = blockIdx.x * blockDim.x + threadIdx.x;
    if (i < D * S) {
        int n = i / S, k = i % S;
        g_W1b[i] = __float2bfloat16(W1[k * D + n]);
    }
    if (i < 4 * D * S) {
        int ck = i / (D * S), rem = i % (D * S);
        int n = rem / S, kl = rem % S;
        g_Wgb[i] = __float2bfloat16(Wg[(ck * S + kl) * D + n]);
        g_Ws1b[i] = __float2bfloat16(Ws1[(ck * S + kl) * D + n]);
    }
}

// ---------------- K1: h stats + bf16 emit + BN1 stats of sub@W1+b1 ----------------
__global__ __launch_bounds__(NT, 2) void k_pass1(const float* __restrict__ h,
                                                 const float* __restrict__ sub,
                                                 const int* __restrict__ batch,
                                                 const float* __restrict__ b1, int N) {
    bf16* Sb = (bf16*)dynsmem;                 // [128][LDWB]
    bf16* Wp = Sb + 128 * LDWB;                // [128][LDWB]
    int* gid = (int*)(Wp + 128 * LDWB);        // [128]
    int tid = threadIdx.x, lane = tid & 31, warp = tid >> 5;
    int wm = warp >> 1, wn = warp & 1;
    int r0 = blockIdx.x * 128;

    load_wchunk(Wp, g_W1b, tid);
    cp_commit();
    if (tid < 128) gid[tid] = batch[min(r0 + tid, N - 1)];

    // sub: fp32 -> bf16 into Sb smem + g_subb global
    for (int i = tid; i < 128 * 32; i += NT) {
        int r = i >> 5, p2 = i & 31;
        int rr = min(r0 + r, N - 1);
        float2 v = *(const float2*)(sub + (size_t)rr * S + p2 * 2);
        unsigned w = pk(v.x, v.y);
        *(unsigned*)(Sb + r * LDWB + p2 * 2) = w;
        if (r0 + r < N) *(unsigned*)(g_subb + (size_t)(r0 + r) * S + p2 * 2) = w;
    }
    // h: fp32 -> bf16 global copy
    for (int i = tid; i < 128 * 64; i += NT) {
        int r = i >> 6, p2 = i & 63;
        if (r0 + r < N) {
            float2 v = *(const float2*)(h + (size_t)(r0 + r) * D + p2 * 2);
            *(unsigned*)(g_hb + (size_t)(r0 + r) * D + p2 * 2) = pk(v.x, v.y);
        }
    }
    __syncthreads();

    // --- h segment stats (fp32, column-owner, run-length flush): 2 halves x 64 rows ---
    {
        int c = tid & 127, half = tid >> 7;
        int rbeg = half * 64;
        float s = 0.f, ss = 0.f, cf = 0.f;
        int cur = gid[rbeg];
        for (int i = 0; i < 64; i += 4) {
            float v[4];
#pragma unroll
            for (int j = 0; j < 4; j++) {
                int r = r0 + rbeg + i + j;
                v[j] = (r < N) ? h[(size_t)r * D + c] : 0.f;
            }
#pragma unroll
            for (int j = 0; j < 4; j++) {
                int rr = rbeg + i + j;
                int g = gid[rr];
                if (g != cur) {
                    atomicAdd(&g_hs[cur * D + c], s);
                    atomicAdd(&g_hss[cur * D + c], ss);
                    if (c == 0) atomicAdd(&g_cnt[cur], cf);
                    s = 0.f; ss = 0.f; cf = 0.f; cur = g;
                }
                if (r0 + rr < N) { s += v[j]; ss += v[j] * v[j]; cf += 1.f; }
            }
        }
        atomicAdd(&g_hs[cur * D + c], s);
        atomicAdd(&g_hss[cur * D + c], ss);
        if (c == 0) atomicAdd(&g_cnt[cur], cf);
    }

    // --- BN1 stats via bf16 mma from accumulators ---
    cp_wait<0>();
    __syncthreads();

    float acc[2][8][4];
#pragma unroll
    for (int mt = 0; mt < 2; mt++)
#pragma unroll
        for (int nt = 0; nt < 8; nt++)
#pragma unroll
            for (int e = 0; e < 4; e++) acc[mt][nt][e] = 0.f;

    mma_chunk(acc, Sb, LDWB, 0, Wp, wm, wn, lane);

    int g4 = lane >> 2, t4 = lane & 3;
#pragma unroll
    for (int nt = 0; nt < 8; nt++)
#pragma unroll
        for (int par = 0; par < 2; par++) {
            int ccol = wn * 64 + nt * 8 + t4 * 2 + par;
            float bb = b1[ccol];
            float s1 = 0.f, s2 = 0.f;
#pragma unroll
            for (int mt = 0; mt < 2; mt++)
#pragma unroll
                for (int rh = 0; rh < 2; rh++) {
                    int r = r0 + wm * 32 + mt * 16 + g4 + rh * 8;
                    float val = acc[mt][nt][rh * 2 + par] + bb;
                    if (r < N) { s1 += val; s2 += val * val; }
                }
#pragma unroll
            for (int o = 4; o < 32; o <<= 1) {
                s1 += __shfl_xor_sync(0xffffffffu, s1, o);
                s2 += __shfl_xor_sync(0xffffffffu, s2, o);
            }
            if (g4 == 0) {
                atomicAdd(&g_bn1sum[ccol], s1);
                atomicAdd(&g_bn1sq[ccol], s2);
            }
        }
}

// ---------------- K2: graph stat finalize + BN1 finalize ----------------
__global__ void k_mid(const float* __restrict__ gam, const float* __restrict__ bet, float invN) {
    int i = blockIdx.x * blockDim.x + threadIdx.x;
    if (i < G * D) {
        int g = i / D;
        float cnt = fmaxf(g_cnt[g], 1.f);
        float m = g_hs[i] / cnt;
        float v = g_hss[i] / cnt - m * m;
        float sd = sqrtf(fmaxf(v, 1e-8f));
        g_gm[i] = m;
        g_gisd[i] = 1.f / (sd + 1e-8f);
    }
    if (blockIdx.x == 0 && threadIdx.x < D) {
        int c = threadIdx.x;
        float mu = g_bn1sum[c] * invN;
        float var = g_bn1sq[c] * invN - mu * mu;
        float inv = rsqrtf(var + 1e-5f);
        g_a1[c] = gam[c] * inv;
        g_c1[c] = bet[c] - mu * gam[c] * inv;
    }
}

__global__ void k_bnfin2(const float* __restrict__ gam, const float* __restrict__ bet, float invN) {
    int i = threadIdx.x;
    float mu = g_bn2sum[i] * invN;
    float var = g_bn2sq[i] * invN - mu * mu;
    float inv = rsqrtf(var + 1e-5f);
    g_a2[i] = gam[i] * inv;
    g_c2[i] = bet[i] - mu * gam[i] * inv;
}

// ---------------- K3: big fused pass (bf16 tiles, 2 CTAs/SM) ----------------
__global__ __launch_bounds__(NT, 2) void k_fused(
    const int* __restrict__ batch,
    const float* __restrict__ b1, const float* __restrict__ bg,
    const float* __restrict__ bs1, int N) {
    bf16* Hb = (bf16*)dynsmem;                 // [128][LDH]  h -> h_dev
    bf16* Eb = Hb + 128 * LDH;                 // [128][LDH]  sub_e -> h_fused
    bf16* Wq = Eb + 128 * LDH;                 // [128][LDWB] Sb, then pong
    bf16* Wp = Wq + 128 * LDWB;                // [128][LDWB] W1, then ping
    float* pa1 = (float*)(Wp + 128 * LDWB);
    float* pc1 = pa1 + D;
    float* pb1 = pc1 + D;
    float* pbg = pb1 + D;
    float* pbs1 = pbg + D;
    int* gid = (int*)(pbs1 + D);               // [128]

    int tid = threadIdx.x, lane = tid & 31, warp = tid >> 5;
    int wm = warp >> 1, wn = warp & 1;
    int g4 = lane >> 2, t4 = lane & 3;
    int r0 = blockIdx.x * 128;

    // G1: Sb(sub bf16) + Wp(W1 bf16); G2: Hb(h bf16)
#pragma unroll
    for (int j = 0; j < 4; j++) {
        int idx = tid + j * NT;
        int r = idx >> 3, f = idx & 7;
        int rr = min(r0 + r, N - 1);
        cp16(Wq + r * LDWB + f * 8, g_subb + (size_t)rr * S + f * 8);
    }
    load_wchunk(Wp, g_W1b, tid);
    cp_commit();
#pragma unroll
    for (int j = 0; j < 8; j++) {
        int idx = tid + j * NT;
        int r = idx >> 4, f = idx & 15;
        int rr = min(r0 + r, N - 1);
        cp16(Hb + r * LDH + f * 8, g_hb + (size_t)rr * D + f * 8);
    }
    cp_commit();

    if (tid < 128) {
        pa1[tid] = g_a1[tid]; pc1[tid] = g_c1[tid]; pb1[tid] = b1[tid];
        pbg[tid] = bg[tid]; pbs1[tid] = bs1[tid];
        gid[tid] = batch[min(r0 + tid, N - 1)];
    }

    float acc[2][8][4];
#pragma unroll
    for (int mt = 0; mt < 2; mt++)
#pragma unroll
        for (int nt = 0; nt < 8; nt++)
#pragma unroll
            for (int e = 0; e < 4; e++) acc[mt][nt][e] = 0.f;

    // ---- mma1: X1 = sub @ W1 ----
    cp_wait<1>();
    __syncthreads();
    mma_chunk(acc, Wq, LDWB, 0, Wp, wm, wn, lane);

    // sub_e epilogue -> Eb (bf16 pairs)
#pragma unroll
    for (int mt = 0; mt < 2; mt++)
#pragma unroll
        for (int nt = 0; nt < 8; nt++)
#pragma unroll
            for (int rh = 0; rh < 2; rh++) {
                int r = wm * 32 + mt * 16 + g4 + rh * 8;
                int c = wn * 64 + nt * 8 + 2 * t4;
                float x0 = acc[mt][nt][rh * 2 + 0] + pb1[c];
                float x1 = acc[mt][nt][rh * 2 + 1] + pb1[c + 1];
                float e0 = fmaxf(pa1[c] * x0 + pc1[c], 0.f);
                float e1 = fmaxf(pa1[c + 1] * x1 + pc1[c + 1], 0.f);
                *(unsigned*)(Eb + r * LDH + c) = pk(e0, e1);
                acc[mt][nt][rh * 2 + 0] = 0.f;
                acc[mt][nt][rh * 2 + 1] = 0.f;
            }
    __syncthreads();

    const bf16* Wtab[8] = { g_Wgb, g_Wgb + 8192, g_Wgb + 16384, g_Wgb + 24576,
                            g_Ws1b, g_Ws1b + 8192, g_Ws1b + 16384, g_Ws1b + 24576 };
    load_wchunk(Wp, Wtab[0], tid); cp_commit();
    load_wchunk(Wq, Wtab[1], tid); cp_commit();

#pragma unroll 1
    for (int k = 0; k < 8; k++) {
        if (k < 6) cp_wait<1>(); else cp_wait<0>();
        __syncthreads();
        bf16* buf = (k & 1) ? Wq : Wp;
        // A: k0,k1 <- Hb(h); k2,k3 <- Eb(sub_e); k4,k5 <- Eb(h_fused); k6,k7 <- Hb(h_dev)
        const bf16* A = (k < 2) ? Hb : (k < 6) ? Eb : Hb;
        mma_chunk(acc, A, LDH, (k & 1) * 64, buf, wm, wn, lane);
        __syncthreads();
        if (k + 2 < 8) { load_wchunk(buf, Wtab[k + 2], tid); cp_commit(); }

        if (k == 3) {
            // gate epilogue: h_fused = h + sigmoid(acc+bg)*sub_e
#pragma unroll
            for (int mt = 0; mt < 2; mt++)
#pragma unroll
                for (int nt = 0; nt < 8; nt++)
#pragma unroll
                    for (int rh = 0; rh < 2; rh++) {
                        int r = wm * 32 + mt * 16 + g4 + rh * 8;
                        int c = wn * 64 + nt * 8 + 2 * t4;
                        float gx0 = acc[mt][nt][rh * 2 + 0] + pbg[c];
                        float gx1 = acc[mt][nt][rh * 2 + 1] + pbg[c + 1];
                        float gt0 = 1.f / (1.f + expf(-gx0));
                        float gt1 = 1.f / (1.f + expf(-gx1));
                        float h0, h1, s0, s1;
                        upk(*(const unsigned*)(Hb + r * LDH + c), h0, h1);
                        upk(*(const unsigned*)(Eb + r * LDH + c), s0, s1);
                        float f0 = h0 + gt0 * s0;
                        float f1 = h1 + gt1 * s1;
                        if (r0 + r < N)
                            *(float2*)(g_hfused + (size_t)(r0 + r) * D + c) = make_float2(f0, f1);
                        *(unsigned*)(Eb + r * LDH + c) = pk(f0, f1);
                        acc[mt][nt][rh * 2 + 0] = 0.f;
                        acc[mt][nt][rh * 2 + 1] = 0.f;
                    }
            __syncthreads();
            // Hb: h -> h_dev
            for (int i = tid; i < 128 * 64; i += NT) {
                int r = i >> 6, c = (i & 63) * 2;
                int g = gid[r];
                float h0, h1;
                upk(*(const unsigned*)(Hb + r * LDH + c), h0, h1);
                float2 m2 = *(const float2*)(g_gm + g * D + c);
                float2 i2 = *(const float2*)(g_gisd + g * D + c);
                *(unsigned*)(Hb + r * LDH + c) = pk((h0 - m2.x) * i2.x, (h1 - m2.y) * i2.y);
            }
            __syncthreads();
        }
    }

    // mma3 epilogue: Z1 fp32 straight to global + BN2 stats from accumulators
#pragma unroll
    for (int mt = 0; mt < 2; mt++)
#pragma unroll
        for (int nt = 0; nt < 8; nt++)
#pragma unroll
            for (int rh = 0; rh < 2; rh++) {
                int r = wm * 32 + mt * 16 + g4 + rh * 8;
                int c = wn * 64 + nt * 8 + 2 * t4;
                if (r0 + r < N) {
                    float z0 = acc[mt][nt][rh * 2 + 0] + pbs1[c];
                    float z1 = acc[mt][nt][rh * 2 + 1] + pbs1[c + 1];
                    *(float2*)(g_Z1 + (size_t)(r0 + r) * D + c) = make_float2(z0, z1);
                }
            }
#pragma unroll
    for (int nt = 0; nt < 8; nt++)
#pragma unroll
        for (int par = 0; par < 2; par++) {
            int ccol = wn * 64 + nt * 8 + 2 * t4 + par;
            float bb = pbs1[ccol];
            float s1 = 0.f, s2 = 0.f;
#pragma unroll
            for (int mt = 0; mt < 2; mt++)
#pragma unroll
                for (int rh = 0; rh < 2; rh++) {
                    int r = r0 + wm * 32 + mt * 16 + g4 + rh * 8;
                    float val = acc[mt][nt][rh * 2 + par] + bb;
                    if (r < N) { s1 += val; s2 += val * val; }
                }
#pragma unroll
            for (int o = 4; o < 32; o <<= 1) {
                s1 += __shfl_xor_sync(0xffffffffu, s1, o);
                s2 += __shfl_xor_sync(0xffffffffu, s2, o);
            }
            if (g4 == 0) {
                atomicAdd(&g_bn2sum[ccol], s1);
                atomicAdd(&g_bn2sq[ccol], s2);
            }
        }
}

// ---------------- K5: logits + exp + weighted segment sums ----------------
__global__ __launch_bounds__(256) void k_score(const int* __restrict__ batch,
                                               const float* __restrict__ Ws2,
                                               const float* __restrict__ bs2, int N) {
    __shared__ float es[256];
    __shared__ int gid[256];
    int tid = threadIdx.x, lane = tid & 31, warp = tid >> 5;
    int r0 = blockIdx.x * 256;
    int nr = min(256, N - r0);
    gid[tid] = batch[min(r0 + min(tid, nr - 1), N - 1)];

    float a2v[4], c2v[4], wv[4];
#pragma unroll
    for (int j = 0; j < 4; j++) {
        int c = lane + 32 * j;
        a2v[j] = g_a2[c]; c2v[j] = g_c2[c]; wv[j] = Ws2[c];
    }
    float bsv = bs2[0];

    int rbase = warp * 32;
    for (int rr = rbase; rr < rbase + 32; rr++) {
        if (rr >= nr) { if (lane == 0) es[rr] = 0.f; continue; }
        const float* z = g_Z1 + (size_t)(r0 + rr) * D;
        float p = 0.f;
#pragma unroll
        for (int j = 0; j < 4; j++) {
            float zz = z[lane + 32 * j];
            p += fmaxf(a2v[j] * zz + c2v[j], 0.f) * wv[j];
        }
#pragma unroll
        for (int o = 16; o > 0; o >>= 1) p += __shfl_xor_sync(0xffffffffu, p, o);
        if (lane == 0) es[rr] = expf(p + bsv);
    }
    __syncthreads();

    int c = tid & 127, half = tid >> 7;
    int rb = half * 128;
    float accn = 0.f, accd = 0.f;
    int cur = gid[rb];
    for (int i = 0; i < 128; i += 4) {
        float v[4], e[4];
#pragma unroll
        for (int j = 0; j < 4; j++) {
            int rr = rb + i + j;
            int r = r0 + rr;
            v[j] = (r < N) ? g_hfused[(size_t)r * D + c] : 0.f;
            e[j] = es[rr];
        }
#pragma unroll
        for (int j = 0; j < 4; j++) {
            int rr = rb + i + j;
            int g = gid[rr];
            if (g != cur) {
                atomicAdd(&g_num[cur * D + c], accn);
                if (c == 0) atomicAdd(&g_den[cur], accd);
                accn = 0.f; accd = 0.f; cur = g;
            }
            if (r0 + rr < N) { accn += e[j] * v[j]; accd += e[j]; }
        }
    }
    atomicAdd(&g_num[cur * D + c], accn);
    if (c == 0) atomicAdd(&g_den[cur], accd);
}

// ---------------- K6: final combine ----------------
__global__ void k_out(float* __restrict__ out, const float* __restrict__ mix) {
    int i = blockIdx.x * blockDim.x + threadIdx.x;
    if (i >= G * D) return;
    int g = i / D;
    float alpha = 1.f / (1.f + expf(-mix[0]));
    float den = g_den[g];
    float wf = (den > 0.f) ? (g_num[i] / den) : 0.f;
    out[i] = alpha * wf + (1.f - alpha) * g_gm[i];
}

// ---------------- launch ----------------
extern "C" void kernel_launch(void* const* d_in, const int* in_sizes, int n_in,
                              void* d_out, int out_size) {
    const float* h   = (const float*)d_in[0];
    const float* sub = (const float*)d_in[1];
    const int* batch = (const int*)d_in[2];
    const float* W1  = (const float*)d_in[3];
    const float* b1  = (const float*)d_in[4];
    const float* g1  = (const float*)d_in[5];
    const float* be1 = (const float*)d_in[6];
    const float* Wg  = (const float*)d_in[7];
    const float* bg  = (const float*)d_in[8];
    const float* Ws1 = (const float*)d_in[9];
    const float* bs1 = (const float*)d_in[10];
    const float* g2  = (const float*)d_in[11];
    const float* be2 = (const float*)d_in[12];
    const float* Ws2 = (const float*)d_in[13];
    const float* bs2 = (const float*)d_in[14];
    const float* mix = (const float*)d_in[15];
    float* out = (float*)d_out;

    int N = in_sizes[0] / D;
    if (N > NMAX) N = NMAX;

    const int SMEM_P1 = 2 * 128 * LDWB * 2 + 512;
    const int SMEM_K3 = (2 * 128 * LDH + 2 * 128 * LDWB) * 2 + 5 * D * 4 + 512;
    cudaFuncSetAttribute(k_pass1, cudaFuncAttributeMaxDynamicSharedMemorySize, SMEM_P1);
    cudaFuncSetAttribute(k_fused, cudaFuncAttributeMaxDynamicSharedMemorySize, SMEM_K3);

    int nb = (N + 127) / 128;
    int nb2 = (N + 255) / 256;
    k_zero<<<(G * D + 255) / 256, 256>>>();
    k_prep<<<(4 * D * S + 255) / 256, 256>>>(W1, Wg, Ws1);
    k_pass1<<<nb, NT, SMEM_P1>>>(h, sub, batch, b1, N);
    k_mid<<<(G * D + 255) / 256, 256>>>(g1, be1, 1.f / (float)N);
    k_fused<<<nb, NT, SMEM_K3>>>(batch, b1, bg, bs1, N);
    k_bnfin2<<<1, 128>>>(g2, be2, 1.f / (float)N);
    k_score<<<nb2, 256>>>(batch, Ws2, bs2, N);
    k_out<<<(G * D + 255) / 256, 256>>>(out, mix);
}